// round 16
// baseline (speedup 1.0000x reference)
#include <cuda_runtime.h>
#include <cstddef>

// FINAL (champion, R11/R15): Depthwise 4x4 FIR conv, stride-2 downsample,
// zero pad (1,1,1,1). x: (16,512,64,64) f32 -> out: (16,512,32,32) f32.
//
// bench 29.1us / ncu 25.1-26.2us (run noise) / DRAM 72-75% (~5.7-6.0 TB/s)
// = compulsory traffic at the measured achievable HBM ceiling for this
// mixed read/write stream. Plateau confirmed across store-policy,
// occupancy (31-54%), prefetch-depth (2-4), thread-granularity (2/4-row),
// and pipeline-structure (flat/ring/persistent) scans in R8-R15.
//
// Design: no shared memory, no barriers. One plane per 128-thread CTA
// (grid 8192). Each thread computes a 2x4 output block (rows 2b,2b+1; cols
// 4c..4c+3) from 6 input rows x 10 cols: core 8 cols via two aligned
// LDG.128, +/-1 halo cols via __shfl width=8 (plane edges -> zero pad).
// Depth-3 rolling prefetch keeps ~3 LDG.128 per thread continuously in
// flight (burst-then-idle duty cycle was the R2-R7 bottleneck). Row indices
// clamped to [0,63] for branch-free loads; the single out-of-range row per
// edge thread is zeroed in registers. Rank-1 weight factorization (exact:
// make_resample_kernel builds k as an outer product) halves weight regs and
// the h-pass FMA live set: u[i]=k[3-i][0]/k[0][0], v[j]=k[0][3-j].

#define IN_W 64
#define OUT_W 32

__global__ __launch_bounds__(128, 8)
void upfirdn_down2_kernel(const float* __restrict__ x,
                          const float* __restrict__ k,
                          float* __restrict__ out,
                          int n_planes)
{
    const int tid = threadIdx.x;
    const int c   = tid & 7;          // col group: output cols 4c..4c+3
    const int b   = tid >> 3;         // row block: output rows 2b, 2b+1 (0..15)
    const int plane = blockIdx.x;
    if (plane >= n_planes) return;

    // Rank-1 factorization of the flipped 4x4 (exact for outer-product FIR).
    const float rk00 = 1.0f / __ldg(&k[0]);
    float u[4], v[4];
    #pragma unroll
    for (int t = 0; t < 4; t++) {
        v[t] = __ldg(&k[3 - t]);              // k[0][3-t]
        u[t] = __ldg(&k[(3 - t) * 4]) * rk00; // k[3-t][0] / k[0][0]
    }

    const float4* __restrict__ xin =
        (const float4*)(x + (size_t)plane * (IN_W * IN_W));

    // Clamped row offsets in float4 units (row r = 4b-1+j, j=0..5).
    int ro[6];
    #pragma unroll
    for (int j = 0; j < 6; j++) {
        int r = 4 * b - 1 + j;
        ro[j] = min(max(r, 0), IN_W - 1) * (IN_W / 4) + c * 2;
    }

    float4 A[6], B[6];
    // Prologue: rows 0..2 in flight (depth-3 pipeline).
    #pragma unroll
    for (int j = 0; j < 3; j++) { A[j] = __ldg(xin + ro[j]); B[j] = __ldg(xin + ro[j] + 1); }

    float acc0[4] = {0.f, 0.f, 0.f, 0.f};
    float acc1[4] = {0.f, 0.f, 0.f, 0.f};

    #pragma unroll
    for (int j = 0; j < 6; j++) {
        // Keep the pipe fed: issue row j+3 before consuming row j.
        if (j < 3) { A[j + 3] = __ldg(xin + ro[j + 3]); B[j + 3] = __ldg(xin + ro[j + 3] + 1); }

        float4 a  = A[j];
        float4 bb = B[j];
        // Zero the (at most one) out-of-range row. Uniform within the 8-lane
        // segment (same b, same j), so shuffles below stay consistent.
        if ((j == 0 && b == 0) || (j == 5 && b == 15)) {
            a  = make_float4(0.f, 0.f, 0.f, 0.f);
            bb = a;
        }
        float vl = __shfl_up_sync(0xffffffffu, bb.w, 1, 8);   // col 8c-1
        float vr = __shfl_down_sync(0xffffffffu, a.x, 1, 8);  // col 8c+8
        if (c == 0) vl = 0.f;
        if (c == 7) vr = 0.f;

        float val[10];
        val[0] = vl;
        val[1] = a.x;  val[2] = a.y;  val[3] = a.z;  val[4] = a.w;
        val[5] = bb.x; val[6] = bb.y; val[7] = bb.z; val[8] = bb.w;
        val[9] = vr;

        // Horizontal pass: 4 taps -> per-output-col row sums.
        float h0 = 0.f, h1 = 0.f, h2 = 0.f, h3 = 0.f;
        #pragma unroll
        for (int t = 0; t < 4; t++) {
            h0 = fmaf(val[0 + t], v[t], h0);
            h1 = fmaf(val[2 + t], v[t], h1);
            h2 = fmaf(val[4 + t], v[t], h2);
            h3 = fmaf(val[6 + t], v[t], h3);
        }

        // Vertical pass: row j is tap j for out-row 2b (j<4), tap j-2 for 2b+1.
        if (j < 4) {
            const float uj = u[j];
            acc0[0] = fmaf(h0, uj, acc0[0]);
            acc0[1] = fmaf(h1, uj, acc0[1]);
            acc0[2] = fmaf(h2, uj, acc0[2]);
            acc0[3] = fmaf(h3, uj, acc0[3]);
        }
        if (j >= 2) {
            const float uj = u[j - 2];
            acc1[0] = fmaf(h0, uj, acc1[0]);
            acc1[1] = fmaf(h1, uj, acc1[1]);
            acc1[2] = fmaf(h2, uj, acc1[2]);
            acc1[3] = fmaf(h3, uj, acc1[3]);
        }
    }

    float* o = out + (size_t)plane * (OUT_W * OUT_W) + (2 * b) * OUT_W + c * 4;
    __stcs((float4*)o,           make_float4(acc0[0], acc0[1], acc0[2], acc0[3]));
    __stcs((float4*)(o + OUT_W), make_float4(acc1[0], acc1[1], acc1[2], acc1[3]));
}

extern "C" void kernel_launch(void* const* d_in, const int* in_sizes, int n_in,
                              void* d_out, int out_size)
{
    int xi = 0, ki = 1;
    if (n_in >= 2 && in_sizes[0] < in_sizes[1]) { xi = 1; ki = 0; }

    const float* x = (const float*)d_in[xi];
    const float* k = (const float*)d_in[ki];
    float* out = (float*)d_out;

    const int n_planes = in_sizes[xi] / (IN_W * IN_W);   // 8192

    upfirdn_down2_kernel<<<n_planes, 128>>>(x, k, out, n_planes);
}

// round 17
// speedup vs baseline: 1.0088x; 1.0088x over previous
#include <cuda_runtime.h>
#include <cstddef>

// FINAL (champion, stable across R11/R15/R16 reruns): Depthwise 4x4 FIR
// conv, stride-2 downsample, zero pad (1,1,1,1).
// x: (16,512,64,64) f32 -> out: (16,512,32,32) f32.
//
// bench 29.1-29.4us / ncu 25.1+-1us / DRAM ~75% (~5.93 TB/s) = compulsory
// traffic at the measured achievable HBM ceiling for this mixed read/write
// stream on sm_103a. Plateau confirmed across store-policy, occupancy
// (31-54%), prefetch-depth (2-4), thread-granularity (2/4-row), and
// pipeline-structure (flat/burst/ring/persistent) scans over 16 rounds.
//
// Design: no shared memory, no barriers. One plane per 128-thread CTA
// (grid 8192). Each thread computes a 2x4 output block (rows 2b,2b+1; cols
// 4c..4c+3) from 6 input rows x 10 cols: core 8 cols via two aligned
// LDG.128, +/-1 halo cols via __shfl width=8 (plane edges -> zero pad).
// Depth-3 rolling prefetch keeps ~3 LDG.128 per thread continuously in
// flight (burst-then-idle duty cycle was the R2-R7 bottleneck). Row indices
// clamped to [0,63] for branch-free loads; the single out-of-range row per
// edge thread is zeroed in registers. Rank-1 weight factorization (exact:
// make_resample_kernel builds k as an outer product) halves weight regs and
// the h-pass FMA live set: u[i]=k[3-i][0]/k[0][0], v[j]=k[0][3-j].

#define IN_W 64
#define OUT_W 32

__global__ __launch_bounds__(128, 8)
void upfirdn_down2_kernel(const float* __restrict__ x,
                          const float* __restrict__ k,
                          float* __restrict__ out,
                          int n_planes)
{
    const int tid = threadIdx.x;
    const int c   = tid & 7;          // col group: output cols 4c..4c+3
    const int b   = tid >> 3;         // row block: output rows 2b, 2b+1 (0..15)
    const int plane = blockIdx.x;
    if (plane >= n_planes) return;

    // Rank-1 factorization of the flipped 4x4 (exact for outer-product FIR).
    const float rk00 = 1.0f / __ldg(&k[0]);
    float u[4], v[4];
    #pragma unroll
    for (int t = 0; t < 4; t++) {
        v[t] = __ldg(&k[3 - t]);              // k[0][3-t]
        u[t] = __ldg(&k[(3 - t) * 4]) * rk00; // k[3-t][0] / k[0][0]
    }

    const float4* __restrict__ xin =
        (const float4*)(x + (size_t)plane * (IN_W * IN_W));

    // Clamped row offsets in float4 units (row r = 4b-1+j, j=0..5).
    int ro[6];
    #pragma unroll
    for (int j = 0; j < 6; j++) {
        int r = 4 * b - 1 + j;
        ro[j] = min(max(r, 0), IN_W - 1) * (IN_W / 4) + c * 2;
    }

    float4 A[6], B[6];
    // Prologue: rows 0..2 in flight (depth-3 pipeline).
    #pragma unroll
    for (int j = 0; j < 3; j++) { A[j] = __ldg(xin + ro[j]); B[j] = __ldg(xin + ro[j] + 1); }

    float acc0[4] = {0.f, 0.f, 0.f, 0.f};
    float acc1[4] = {0.f, 0.f, 0.f, 0.f};

    #pragma unroll
    for (int j = 0; j < 6; j++) {
        // Keep the pipe fed: issue row j+3 before consuming row j.
        if (j < 3) { A[j + 3] = __ldg(xin + ro[j + 3]); B[j + 3] = __ldg(xin + ro[j + 3] + 1); }

        float4 a  = A[j];
        float4 bb = B[j];
        // Zero the (at most one) out-of-range row. Uniform within the 8-lane
        // segment (same b, same j), so shuffles below stay consistent.
        if ((j == 0 && b == 0) || (j == 5 && b == 15)) {
            a  = make_float4(0.f, 0.f, 0.f, 0.f);
            bb = a;
        }
        float vl = __shfl_up_sync(0xffffffffu, bb.w, 1, 8);   // col 8c-1
        float vr = __shfl_down_sync(0xffffffffu, a.x, 1, 8);  // col 8c+8
        if (c == 0) vl = 0.f;
        if (c == 7) vr = 0.f;

        float val[10];
        val[0] = vl;
        val[1] = a.x;  val[2] = a.y;  val[3] = a.z;  val[4] = a.w;
        val[5] = bb.x; val[6] = bb.y; val[7] = bb.z; val[8] = bb.w;
        val[9] = vr;

        // Horizontal pass: 4 taps -> per-output-col row sums.
        float h0 = 0.f, h1 = 0.f, h2 = 0.f, h3 = 0.f;
        #pragma unroll
        for (int t = 0; t < 4; t++) {
            h0 = fmaf(val[0 + t], v[t], h0);
            h1 = fmaf(val[2 + t], v[t], h1);
            h2 = fmaf(val[4 + t], v[t], h2);
            h3 = fmaf(val[6 + t], v[t], h3);
        }

        // Vertical pass: row j is tap j for out-row 2b (j<4), tap j-2 for 2b+1.
        if (j < 4) {
            const float uj = u[j];
            acc0[0] = fmaf(h0, uj, acc0[0]);
            acc0[1] = fmaf(h1, uj, acc0[1]);
            acc0[2] = fmaf(h2, uj, acc0[2]);
            acc0[3] = fmaf(h3, uj, acc0[3]);
        }
        if (j >= 2) {
            const float uj = u[j - 2];
            acc1[0] = fmaf(h0, uj, acc1[0]);
            acc1[1] = fmaf(h1, uj, acc1[1]);
            acc1[2] = fmaf(h2, uj, acc1[2]);
            acc1[3] = fmaf(h3, uj, acc1[3]);
        }
    }

    float* o = out + (size_t)plane * (OUT_W * OUT_W) + (2 * b) * OUT_W + c * 4;
    __stcs((float4*)o,           make_float4(acc0[0], acc0[1], acc0[2], acc0[3]));
    __stcs((float4*)(o + OUT_W), make_float4(acc1[0], acc1[1], acc1[2], acc1[3]));
}

extern "C" void kernel_launch(void* const* d_in, const int* in_sizes, int n_in,
                              void* d_out, int out_size)
{
    int xi = 0, ki = 1;
    if (n_in >= 2 && in_sizes[0] < in_sizes[1]) { xi = 1; ki = 0; }

    const float* x = (const float*)d_in[xi];
    const float* k = (const float*)d_in[ki];
    float* out = (float*)d_out;

    const int n_planes = in_sizes[xi] / (IN_W * IN_W);   // 8192

    upfirdn_down2_kernel<<<n_planes, 128>>>(x, k, out, n_planes);
}